// round 8
// baseline (speedup 1.0000x reference)
#include <cuda_runtime.h>

#define SEQ  256
#define HID  2048
#define DIM  2048
#define NCTA 128
#define NTHR 1024
#define PINR 22                        // W_hh rows pinned in smem per CTA
#define DYNB (PINR * DIM * 4)          // 180224 bytes dynamic smem

// ---- persistent device state (static allocation: allowed) ----
__device__ float g_Wp[(size_t)NCTA * DIM * 64];   // repacked W_ih: [b][j][64 owned rows]
__device__ __align__(16) float g_h[HID];
__device__ float g_x[DIM];
__device__ volatile unsigned g_c0 = 0;            // barrier channel 0 (x-ready), monotonic
__device__ volatile unsigned g_c1 = 0;            // barrier channel 1 (h-ready), monotonic

// ---- JAX threefry2x32 (exact rounds, partitionable counter layout) ----
__device__ __forceinline__ void tf2x32(unsigned k0, unsigned k1,
                                       unsigned x0, unsigned x1,
                                       unsigned &o0, unsigned &o1) {
  unsigned ks2 = k0 ^ k1 ^ 0x1BD11BDAu;
#define TFR(r) { x0 += x1; x1 = (x1 << (r)) | (x1 >> (32 - (r))); x1 ^= x0; }
  x0 += k0; x1 += k1;
  TFR(13) TFR(15) TFR(26) TFR(6)   x0 += k1;  x1 += ks2 + 1u;
  TFR(17) TFR(29) TFR(16) TFR(24)  x0 += ks2; x1 += k0 + 2u;
  TFR(13) TFR(15) TFR(26) TFR(6)   x0 += k0;  x1 += k1 + 3u;
  TFR(17) TFR(29) TFR(16) TFR(24)  x0 += k1;  x1 += ks2 + 4u;
  TFR(13) TFR(15) TFR(26) TFR(6)   x0 += ks2; x1 += k0 + 5u;
#undef TFR
  o0 = x0; o1 = x1;
}

__device__ __forceinline__ float u01(unsigned bits) {
  return __uint_as_float((bits >> 9) | 0x3f800000u) - 1.0f;
}
__device__ __forceinline__ float sigf(float v) { return 1.0f / (1.0f + expf(-v)); }

extern "C" __global__ void __launch_bounds__(NTHR, 1)
lstm_policy_kernel(const float* __restrict__ A,
                   const float* __restrict__ W_ih,
                   const float* __restrict__ W_hh,
                   const float* __restrict__ b_ih,
                   const float* __restrict__ b_hh,
                   const float* __restrict__ V_w,
                   const float* __restrict__ V_b,
                   const float* __restrict__ temp,
                   float* __restrict__ out)
{
  extern __shared__ float pinW[];     // [PINR][DIM] pinned W_hh rows (176KB)

  const int b    = blockIdx.x;
  const int tid  = threadIdx.x;
  const int lane = tid & 31;
  const int w    = tid >> 5;

  __shared__ float h_s[HID];          // 8KB
  __shared__ int   nzi[DIM];          // 8KB
  __shared__ float nzv[DIM];          // 8KB
  __shared__ float4 part4[64][16];    // 16KB gather partials [seg][gate-quad]
  __shared__ float psumV[16][2];
  __shared__ float2 psum2[32];
  __shared__ float gsum[64];
  __shared__ float c_s[16];
  __shared__ int   wcnt[32];
  __shared__ int   woff[33];

  // ---- one-time repack: g_Wp[b][j][g] = W_ih[row(g)][j] (pinW aliased as staging) ----
  {
    float (*tile)[65] = (float(*)[65])pinW;   // 64x65 staging
    for (int t = 0; t < 32; ++t) {
      int j0 = t * 64;
      for (int gg = w; gg < 64; gg += 32) {
        int row = (gg >> 4) * HID + b * 16 + (gg & 15);
        for (int jj = lane; jj < 64; jj += 32)
          tile[jj][gg] = W_ih[(size_t)row * DIM + j0 + jj];
      }
      __syncthreads();
      for (int jj = w; jj < 64; jj += 32) {
        float* dst = &g_Wp[((size_t)b * DIM + j0 + jj) * 64];
        for (int gg = lane; gg < 64; gg += 32) dst[gg] = tile[jj][gg];
      }
      __syncthreads();
    }
  }
  __syncthreads();
  // ---- one-time: pin W_hh rows for gates 0..PINR-1 of this CTA into smem ----
  for (int g = 0; g < PINR; ++g) {
    int row = (g >> 4) * HID + b * 16 + (g & 15);
    const float* src = W_hh + (size_t)row * DIM;
    for (int i = tid; i < DIM; i += NTHR) pinW[g * DIM + i] = src[i];
  }
  if (tid < 16) c_s[tid] = 0.0f;
  __syncthreads();

  const float temperature = __ldg(temp);
  const float4* H4 = (const float4*)h_s;

  for (int step = 0; step < SEQ; ++step) {
    unsigned sk0, sk1;
    tf2x32(0u, 42u, 0u, (unsigned)step, sk0, sk1);

    // load h into smem
    for (int i = tid; i < HID; i += NTHR)
      h_s[i] = (step == 0) ? 0.0f : __ldcg(&g_h[i]);
    __syncthreads();

    // ====== Phase A1: V_w rows as half-dots (fast x publication) ======
    {
      int r16 = w >> 1, hf = w & 1;
      const float4* R  = (const float4*)(V_w + (size_t)(b * 16 + r16) * DIM) + hf * 256;
      const float4* Hh = H4 + hf * 256;
      float s = 0.0f;
      #pragma unroll
      for (int k = 0; k < 8; ++k) {
        float4 a  = __ldg(R + k * 32 + lane);
        float4 hh = Hh[k * 32 + lane];
        s += a.x * hh.x + a.y * hh.y + a.z * hh.z + a.w * hh.w;
      }
      #pragma unroll
      for (int o = 16; o > 0; o >>= 1) s += __shfl_xor_sync(0xffffffffu, s, o);
      if (lane == 0) psumV[r16][hf] = s;
    }
    __syncthreads();
    if (tid < 16) {
      float sv = psumV[tid][0] + psumV[tid][1];
      int r = b * 16 + tid;
      float z  = temperature * (sv + __ldg(&V_b[r]));
      float pi = sigf(z);
      unsigned y0, y1;
      tf2x32(sk0, sk1, 0u, (unsigned)r, y0, y1);
      float u   = u01(y0 ^ y1);
      float act = (u < pi) ? 1.0f : 0.0f;
      __stcs(&out[(size_t)step * DIM + r], act);
      __stcs(&out[(size_t)SEQ * DIM + (size_t)step * DIM + r], pi);
      __stcg(&g_x[r], act * __ldg(&A[r]));
    }
    __threadfence();
    __syncthreads();
    if (tid == 0) atomicAdd((unsigned*)&g_c0, 1u);   // barrier-1 ARRIVE (hidden)

    // ====== Phase A2: W_hh — gates (w, 32+w); gate w from smem when w<PINR ======
    {
      int lg = 32 + w;
      int rowB = (lg >> 4) * HID + b * 16 + (lg & 15);
      const float4* RB = (const float4*)(W_hh + (size_t)rowB * DIM);
      float sA = 0.0f, sB = 0.0f;
      if (w < PINR) {
        const float4* PA = (const float4*)(pinW + w * DIM);
        #pragma unroll
        for (int k = 0; k < 16; ++k) {
          float4 bb = __ldg(RB + k * 32 + lane);
          float4 a  = PA[k * 32 + lane];
          float4 hh = H4[k * 32 + lane];
          sA += a.x  * hh.x + a.y  * hh.y + a.z  * hh.z + a.w  * hh.w;
          sB += bb.x * hh.x + bb.y * hh.y + bb.z * hh.z + bb.w * hh.w;
        }
      } else {
        int rowA = (w >> 4) * HID + b * 16 + (w & 15);
        const float4* RA = (const float4*)(W_hh + (size_t)rowA * DIM);
        #pragma unroll
        for (int k = 0; k < 16; ++k) {
          float4 a  = __ldg(RA + k * 32 + lane);
          float4 bb = __ldg(RB + k * 32 + lane);
          float4 hh = H4[k * 32 + lane];
          sA += a.x  * hh.x + a.y  * hh.y + a.z  * hh.z + a.w  * hh.w;
          sB += bb.x * hh.x + bb.y * hh.y + bb.z * hh.z + bb.w * hh.w;
        }
      }
      #pragma unroll
      for (int o = 16; o > 0; o >>= 1) {
        sA += __shfl_xor_sync(0xffffffffu, sA, o);
        sB += __shfl_xor_sync(0xffffffffu, sB, o);
      }
      if (lane == 0) psum2[w] = make_float2(sA, sB);
    }
    __syncthreads();
    if (tid < 64) {
      float sv = (tid < 32) ? psum2[tid].x : psum2[tid - 32].y;
      int row = (tid >> 4) * HID + b * 16 + (tid & 15);
      gsum[tid] = sv + __ldg(&b_ih[row]) + __ldg(&b_hh[row]);
    }

    // barrier-1 WAIT: all CTAs' x written
    if (tid == 0) {
      unsigned tgt = (unsigned)NCTA * (unsigned)(step + 1);
      while (g_c0 < tgt) { }
      __threadfence();
    }
    __syncthreads();

    // ====== Phase B: compact nonzeros of x, all-global float4 gather ======
    {
      int base = w * 64;
      float v0 = __ldcg(&g_x[base + lane]);
      float v1 = __ldcg(&g_x[base + 32 + lane]);
      unsigned b0 = __ballot_sync(0xffffffffu, v0 != 0.0f);
      unsigned b1 = __ballot_sync(0xffffffffu, v1 != 0.0f);
      if (lane == 0) wcnt[w] = __popc(b0) + __popc(b1);
      __syncthreads();
      if (w == 0) {
        int c2 = wcnt[lane];
        int xs = c2;
        #pragma unroll
        for (int o = 1; o < 32; o <<= 1) {
          int y = __shfl_up_sync(0xffffffffu, xs, o);
          if (lane >= o) xs += y;
        }
        woff[lane] = xs - c2;
        if (lane == 31) woff[32] = xs;
      }
      __syncthreads();
      int off = woff[w];
      unsigned mlo = (1u << lane) - 1u;
      if (v0 != 0.0f) { int p = off + __popc(b0 & mlo); nzi[p] = base + lane; nzv[p] = v0; }
      if (v1 != 0.0f) { int p = off + __popc(b0) + __popc(b1 & mlo); nzi[p] = base + 32 + lane; nzv[p] = v1; }
      __syncthreads();
    }
    const int len = woff[32];

    {
      const int seg = tid >> 4;           // 64 segments
      const int g4  = tid & 15;           // gate quad (4 gates per thread)
      const float4* wp4 = (const float4*)g_Wp + (size_t)b * (DIM * 16) + g4;
      int kb0 = (len * seg) >> 6;
      int kb1 = (len * (seg + 1)) >> 6;
      float4 acc = make_float4(0.f, 0.f, 0.f, 0.f);
      #pragma unroll 8
      for (int k = kb0; k < kb1; ++k) {
        float4 wv = __ldcs(wp4 + (size_t)nzi[k] * 16);
        float xv = nzv[k];
        acc.x = fmaf(xv, wv.x, acc.x);
        acc.y = fmaf(xv, wv.y, acc.y);
        acc.z = fmaf(xv, wv.z, acc.z);
        acc.w = fmaf(xv, wv.w, acc.w);
      }
      part4[seg][g4] = acc;
    }
    __syncthreads();
    if (tid < 64) {
      float s2 = gsum[tid];
      const int gp = tid >> 2, comp = tid & 3;
      const float* pp = (const float*)&part4[0][gp] + comp;
      #pragma unroll
      for (int s3 = 0; s3 < 64; ++s3) s2 += pp[(size_t)s3 * 64];
      gsum[tid] = s2;
    }
    __syncthreads();

    if (tid < 16) {
      float ig = gsum[tid];
      float fg = gsum[16 + tid];
      float gg = gsum[32 + tid];
      float og = gsum[48 + tid];
      float cn = sigf(fg) * c_s[tid] + sigf(ig) * tanhf(gg);
      float hn = sigf(og) * tanhf(cn);
      c_s[tid] = cn;
      __stcg(&g_h[b * 16 + tid], hn);
    }
    __threadfence();
    __syncthreads();
    if (tid == 0) {                                    // barrier-2 arrive + wait
      atomicAdd((unsigned*)&g_c1, 1u);
      unsigned tgt = (unsigned)NCTA * (unsigned)(step + 1);
      while (g_c1 < tgt) { }
      __threadfence();
    }
    __syncthreads();
  }

  // ---- exit barrier + counter reset (keeps graph replays correct) ----
  __syncthreads();
  if (tid == 0) {
    atomicAdd((unsigned*)&g_c0, 1u);
    if (b == 0) {
      unsigned tgt = (unsigned)NCTA * (unsigned)SEQ + (unsigned)NCTA;
      while (g_c0 < tgt) { }
      g_c0 = 0u;
      g_c1 = 0u;
      __threadfence();
    }
  }
}

extern "C" void kernel_launch(void* const* d_in, const int* in_sizes, int n_in,
                              void* d_out, int out_size) {
  (void)in_sizes; (void)n_in; (void)out_size;
  cudaFuncSetAttribute(lstm_policy_kernel,
                       cudaFuncAttributeMaxDynamicSharedMemorySize, DYNB);
  lstm_policy_kernel<<<NCTA, NTHR, DYNB>>>(
      (const float*)d_in[0],  // A
      (const float*)d_in[1],  // W_ih
      (const float*)d_in[2],  // W_hh
      (const float*)d_in[3],  // b_ih
      (const float*)d_in[4],  // b_hh
      (const float*)d_in[5],  // V_w
      (const float*)d_in[6],  // V_b
      (const float*)d_in[7],  // temperature
      (float*)d_out);
}

// round 9
// speedup vs baseline: 1.0681x; 1.0681x over previous
#include <cuda_runtime.h>

#define SEQ  256
#define HID  2048
#define DIM  2048
#define NCTA 128
#define NTHR 1024
#define PJ   640                      // gather columns pinned in smem
#define DYNB (PJ * 64 * 4)            // 163840 bytes dynamic smem

// ---- persistent device state (static allocation: allowed) ----
__device__ float g_Wp[(size_t)NCTA * DIM * 64];   // repacked W_ih: [b][j][64 owned rows]
__device__ __align__(16) float g_h[HID];
__device__ float g_x[DIM];
__device__ volatile unsigned g_c0 = 0;            // barrier channel 0 (x-ready), monotonic
__device__ volatile unsigned g_c1 = 0;            // barrier channel 1 (h-ready), monotonic

// ---- JAX threefry2x32 (exact rounds, partitionable counter layout) ----
__device__ __forceinline__ void tf2x32(unsigned k0, unsigned k1,
                                       unsigned x0, unsigned x1,
                                       unsigned &o0, unsigned &o1) {
  unsigned ks2 = k0 ^ k1 ^ 0x1BD11BDAu;
#define TFR(r) { x0 += x1; x1 = (x1 << (r)) | (x1 >> (32 - (r))); x1 ^= x0; }
  x0 += k0; x1 += k1;
  TFR(13) TFR(15) TFR(26) TFR(6)   x0 += k1;  x1 += ks2 + 1u;
  TFR(17) TFR(29) TFR(16) TFR(24)  x0 += ks2; x1 += k0 + 2u;
  TFR(13) TFR(15) TFR(26) TFR(6)   x0 += k0;  x1 += k1 + 3u;
  TFR(17) TFR(29) TFR(16) TFR(24)  x0 += k1;  x1 += ks2 + 4u;
  TFR(13) TFR(15) TFR(26) TFR(6)   x0 += ks2; x1 += k0 + 5u;
#undef TFR
  o0 = x0; o1 = x1;
}

__device__ __forceinline__ float u01(unsigned bits) {
  return __uint_as_float((bits >> 9) | 0x3f800000u) - 1.0f;
}
__device__ __forceinline__ float sigf(float v) { return 1.0f / (1.0f + expf(-v)); }

#define BAR_GRP() asm volatile("bar.sync 1, 512;" ::: "memory")

extern "C" __global__ void __launch_bounds__(NTHR, 1)
lstm_policy_kernel(const float* __restrict__ A,
                   const float* __restrict__ W_ih,
                   const float* __restrict__ W_hh,
                   const float* __restrict__ b_ih,
                   const float* __restrict__ b_hh,
                   const float* __restrict__ V_w,
                   const float* __restrict__ V_b,
                   const float* __restrict__ temp,
                   float* __restrict__ out)
{
  extern __shared__ float pinW[];     // [PJ][64] pinned gather columns (160KB)

  const int b    = blockIdx.x;
  const int tid  = threadIdx.x;
  const int lane = tid & 31;
  const int w    = tid >> 5;

  __shared__ float h_s[HID];          // 8KB
  __shared__ int   nzi[DIM];          // 8KB
  __shared__ float nzv[DIM];          // 8KB
  __shared__ float4 part4[32][16];    // 8KB gather partials [seg][gate-quad]
  __shared__ float psumV[16][2];
  __shared__ float psumA[16][4];      // A2 partials: [warp][gate-quarter]
  __shared__ float gsum[64];
  __shared__ float c_s[16];
  __shared__ int   wcnt[16];
  __shared__ int   woff[17];

  // ---- one-time repack: g_Wp[b][j][g] = W_ih[row(g)][j] (pinW aliased as staging) ----
  {
    float (*tile)[65] = (float(*)[65])pinW;   // 64x65 staging
    for (int t = 0; t < 32; ++t) {
      int j0 = t * 64;
      for (int gg = w; gg < 64; gg += 32) {
        int row = (gg >> 4) * HID + b * 16 + (gg & 15);
        for (int jj = lane; jj < 64; jj += 32)
          tile[jj][gg] = W_ih[(size_t)row * DIM + j0 + jj];
      }
      __syncthreads();
      for (int jj = w; jj < 64; jj += 32) {
        float* dst = &g_Wp[((size_t)b * DIM + j0 + jj) * 64];
        for (int gg = lane; gg < 64; gg += 32) dst[gg] = tile[jj][gg];
      }
      __syncthreads();
    }
    // fill pinned gather region from own repacked slice (contiguous copy)
    const float* src = &g_Wp[(size_t)b * DIM * 64];
    for (int i = tid; i < PJ * 64; i += NTHR) pinW[i] = src[i];
  }
  if (tid < 16) c_s[tid] = 0.0f;
  __syncthreads();

  const float temperature = __ldg(temp);
  const float4* H4 = (const float4*)h_s;

  for (int step = 0; step < SEQ; ++step) {
    unsigned sk0, sk1;
    tf2x32(0u, 42u, 0u, (unsigned)step, sk0, sk1);

    // load h into smem
    for (int i = tid; i < HID; i += NTHR)
      h_s[i] = (step == 0) ? 0.0f : __ldcg(&g_h[i]);
    __syncthreads();

    // ====== Phase A1: V_w rows as half-dots (fast x publication), all 32 warps ======
    {
      int r16 = w >> 1, hf = w & 1;
      const float4* R  = (const float4*)(V_w + (size_t)(b * 16 + r16) * DIM) + hf * 256;
      const float4* Hh = H4 + hf * 256;
      float s = 0.0f;
      #pragma unroll
      for (int k = 0; k < 8; ++k) {
        float4 a  = __ldg(R + k * 32 + lane);
        float4 hh = Hh[k * 32 + lane];
        s += a.x * hh.x + a.y * hh.y + a.z * hh.z + a.w * hh.w;
      }
      #pragma unroll
      for (int o = 16; o > 0; o >>= 1) s += __shfl_xor_sync(0xffffffffu, s, o);
      if (lane == 0) psumV[r16][hf] = s;
    }
    __syncthreads();
    if (tid < 16) {
      float sv = psumV[tid][0] + psumV[tid][1];
      int r = b * 16 + tid;
      float z  = temperature * (sv + __ldg(&V_b[r]));
      float pi = sigf(z);
      unsigned y0, y1;
      tf2x32(sk0, sk1, 0u, (unsigned)r, y0, y1);
      float u   = u01(y0 ^ y1);
      float act = (u < pi) ? 1.0f : 0.0f;
      __stcs(&out[(size_t)step * DIM + r], act);
      __stcs(&out[(size_t)SEQ * DIM + (size_t)step * DIM + r], pi);
      __stcg(&g_x[r], act * __ldg(&A[r]));
    }
    __threadfence();
    __syncthreads();
    if (tid == 0) atomicAdd((unsigned*)&g_c0, 1u);   // barrier-1 ARRIVE

    // ====== Warp-specialized overlap ======
    if (w < 16) {
      // ---- producers: all 64 W_hh rows; warp w owns gates {w, w+16, w+32, w+48} ----
      const float4* R0 = (const float4*)(W_hh + (size_t)(0 * HID + b * 16 + w) * DIM);
      const float4* R1 = (const float4*)(W_hh + (size_t)(1 * HID + b * 16 + w) * DIM);
      const float4* R2 = (const float4*)(W_hh + (size_t)(2 * HID + b * 16 + w) * DIM);
      const float4* R3 = (const float4*)(W_hh + (size_t)(3 * HID + b * 16 + w) * DIM);
      float sA = 0.0f, sB = 0.0f, sC = 0.0f, sD = 0.0f;
      #pragma unroll
      for (int k = 0; k < 16; ++k) {
        float4 hh = H4[k * 32 + lane];
        float4 a0 = __ldg(R0 + k * 32 + lane);
        float4 a1 = __ldg(R1 + k * 32 + lane);
        float4 a2 = __ldg(R2 + k * 32 + lane);
        float4 a3 = __ldg(R3 + k * 32 + lane);
        sA += a0.x * hh.x + a0.y * hh.y + a0.z * hh.z + a0.w * hh.w;
        sB += a1.x * hh.x + a1.y * hh.y + a1.z * hh.z + a1.w * hh.w;
        sC += a2.x * hh.x + a2.y * hh.y + a2.z * hh.z + a2.w * hh.w;
        sD += a3.x * hh.x + a3.y * hh.y + a3.z * hh.z + a3.w * hh.w;
      }
      #pragma unroll
      for (int o = 16; o > 0; o >>= 1) {
        sA += __shfl_xor_sync(0xffffffffu, sA, o);
        sB += __shfl_xor_sync(0xffffffffu, sB, o);
        sC += __shfl_xor_sync(0xffffffffu, sC, o);
        sD += __shfl_xor_sync(0xffffffffu, sD, o);
      }
      if (lane == 0) {
        psumA[w][0] = sA; psumA[w][1] = sB; psumA[w][2] = sC; psumA[w][3] = sD;
      }
    } else {
      // ---- consumers: wait for x, compact nonzeros, gather ----
      const int w2 = w - 16;              // 0..15
      if (tid == 512) {
        unsigned tgt = (unsigned)NCTA * (unsigned)(step + 1);
        while (g_c0 < tgt) { }
        __threadfence();
      }
      BAR_GRP();

      // compaction: warp w2 owns g_x[w2*128 .. w2*128+128)
      {
        int base = w2 * 128;
        float v0 = __ldcg(&g_x[base + lane]);
        float v1 = __ldcg(&g_x[base + 32 + lane]);
        float v2 = __ldcg(&g_x[base + 64 + lane]);
        float v3 = __ldcg(&g_x[base + 96 + lane]);
        unsigned b0 = __ballot_sync(0xffffffffu, v0 != 0.0f);
        unsigned b1 = __ballot_sync(0xffffffffu, v1 != 0.0f);
        unsigned b2 = __ballot_sync(0xffffffffu, v2 != 0.0f);
        unsigned b3 = __ballot_sync(0xffffffffu, v3 != 0.0f);
        if (lane == 0) wcnt[w2] = __popc(b0) + __popc(b1) + __popc(b2) + __popc(b3);
        BAR_GRP();
        if (w2 == 0 && lane < 16) {
          int c2 = wcnt[lane];
          int xs = c2;
          #pragma unroll
          for (int o = 1; o < 16; o <<= 1) {
            int y = __shfl_up_sync(0x0000ffffu, xs, o);
            if (lane >= o) xs += y;
          }
          woff[lane] = xs - c2;
          if (lane == 15) woff[16] = xs;
        }
        BAR_GRP();
        int off = woff[w2];
        unsigned mlo = (1u << lane) - 1u;
        int c0 = __popc(b0), c1 = __popc(b1), c2p = __popc(b2);
        if (v0 != 0.0f) { int p = off + __popc(b0 & mlo);                  nzi[p] = base + lane;      nzv[p] = v0; }
        if (v1 != 0.0f) { int p = off + c0 + __popc(b1 & mlo);             nzi[p] = base + 32 + lane; nzv[p] = v1; }
        if (v2 != 0.0f) { int p = off + c0 + c1 + __popc(b2 & mlo);        nzi[p] = base + 64 + lane; nzv[p] = v2; }
        if (v3 != 0.0f) { int p = off + c0 + c1 + c2p + __popc(b3 & mlo);  nzi[p] = base + 96 + lane; nzv[p] = v3; }
        BAR_GRP();
      }
      const int len  = woff[16];
      const int len0 = woff[5];           // nonzeros with j < PJ=640 (5 warp-chunks of 128)

      // gather: 32 segments x 16 gate-quads over 512 threads
      {
        const int ct  = tid - 512;        // 0..511
        const int seg = ct >> 4;          // 0..31
        const int g4  = ct & 15;          // gate quad
        const float4* wp4  = (const float4*)g_Wp + (size_t)b * (DIM * 16) + g4;
        const float4* pin4 = (const float4*)pinW + g4;
        int kb0 = (len * seg) >> 5;
        int kb1 = (len * (seg + 1)) >> 5;
        float4 acc = make_float4(0.f, 0.f, 0.f, 0.f);
        int ks = kb1 < len0 ? kb1 : len0;
        #pragma unroll 4
        for (int k = kb0; k < ks; ++k) {                 // smem-pinned part
          float4 wv = pin4[(size_t)nzi[k] * 16];
          float xv = nzv[k];
          acc.x = fmaf(xv, wv.x, acc.x);
          acc.y = fmaf(xv, wv.y, acc.y);
          acc.z = fmaf(xv, wv.z, acc.z);
          acc.w = fmaf(xv, wv.w, acc.w);
        }
        int kg = kb0 > len0 ? kb0 : len0;
        #pragma unroll 8
        for (int k = kg; k < kb1; ++k) {                 // global streaming part
          float4 wv = __ldcs(wp4 + (size_t)nzi[k] * 16);
          float xv = nzv[k];
          acc.x = fmaf(xv, wv.x, acc.x);
          acc.y = fmaf(xv, wv.y, acc.y);
          acc.z = fmaf(xv, wv.z, acc.z);
          acc.w = fmaf(xv, wv.w, acc.w);
        }
        part4[seg][g4] = acc;
      }
    }
    __syncthreads();   // rejoin producers + consumers

    // ====== Final combine: biases + A2 + gather, then cell update ======
    if (tid < 64) {
      int row = (tid >> 4) * HID + b * 16 + (tid & 15);
      float s2 = psumA[tid & 15][tid >> 4] + __ldg(&b_ih[row]) + __ldg(&b_hh[row]);
      const int gp = tid >> 2, comp = tid & 3;
      const float* pp = (const float*)&part4[0][gp] + comp;
      #pragma unroll
      for (int s3 = 0; s3 < 32; ++s3) s2 += pp[(size_t)s3 * 64];
      gsum[tid] = s2;
    }
    __syncthreads();

    if (tid < 16) {
      float ig = gsum[tid];
      float fg = gsum[16 + tid];
      float gg = gsum[32 + tid];
      float og = gsum[48 + tid];
      float cn = sigf(fg) * c_s[tid] + sigf(ig) * tanhf(gg);
      float hn = sigf(og) * tanhf(cn);
      c_s[tid] = cn;
      __stcg(&g_h[b * 16 + tid], hn);
    }
    __threadfence();
    __syncthreads();
    if (tid == 0) {                                    // barrier-2 arrive + wait
      atomicAdd((unsigned*)&g_c1, 1u);
      unsigned tgt = (unsigned)NCTA * (unsigned)(step + 1);
      while (g_c1 < tgt) { }
      __threadfence();
    }
    __syncthreads();
  }

  // ---- exit barrier + counter reset (keeps graph replays correct) ----
  __syncthreads();
  if (tid == 0) {
    atomicAdd((unsigned*)&g_c0, 1u);
    if (b == 0) {
      unsigned tgt = (unsigned)NCTA * (unsigned)SEQ + (unsigned)NCTA;
      while (g_c0 < tgt) { }
      g_c0 = 0u;
      g_c1 = 0u;
      __threadfence();
    }
  }
}

extern "C" void kernel_launch(void* const* d_in, const int* in_sizes, int n_in,
                              void* d_out, int out_size) {
  (void)in_sizes; (void)n_in; (void)out_size;
  cudaFuncSetAttribute(lstm_policy_kernel,
                       cudaFuncAttributeMaxDynamicSharedMemorySize, DYNB);
  lstm_policy_kernel<<<NCTA, NTHR, DYNB>>>(
      (const float*)d_in[0],  // A
      (const float*)d_in[1],  // W_ih
      (const float*)d_in[2],  // W_hh
      (const float*)d_in[3],  // b_ih
      (const float*)d_in[4],  // b_hh
      (const float*)d_in[5],  // V_w
      (const float*)d_in[6],  // V_b
      (const float*)d_in[7],  // temperature
      (float*)d_out);
}